// round 1
// baseline (speedup 1.0000x reference)
#include <cuda_runtime.h>
#include <math.h>

#define Bn 16
#define Tn 2048
#define Cn 1024
#define Hn 64

// ---- static scratch (no allocations allowed) ----
__device__ float g_qT[(size_t)Bn * Hn * Tn];      // [b][d][t]
__device__ float g_kT[(size_t)Bn * Hn * Tn];      // [b][d][t]
__device__ float g_v [(size_t)Bn * Tn * Hn];      // [b][t][d]
__device__ float g_ST[(size_t)Bn * Tn * Tn];      // [b][s][t]  256MB
__device__ float g_mpart[Bn * 16 * Tn];           // [b][t_tile][s]
__device__ float g_zpart[Bn * 16 * Tn];
__device__ float g_c[Bn * Tn];                    // m + log(Z) per (b,s)

// Fast exp via FMA-pipe polynomial (avoids MUFU bottleneck).
// Valid for x <= 0 (our arguments are always <= 0); clamps to 0 for very negative x.
__device__ __forceinline__ float fast_exp(float x) {
    float y = fmaxf(x * 1.4426950408889634f, -126.0f);
    float z = y + 12582912.0f;                 // round-to-nearest-int trick
    int   i = __float_as_int(z) - 0x4B400000;  // integer part
    float f = y - (z - 12582912.0f);           // fraction in [-0.5, 0.5]
    float p = 1.3333558146428443e-3f;          // 2^f Taylor, err ~2e-6
    p = fmaf(p, f, 9.618129107628477e-3f);
    p = fmaf(p, f, 5.550410866482158e-2f);
    p = fmaf(p, f, 2.402265069591007e-1f);
    p = fmaf(p, f, 6.931471805599453e-1f);
    p = fmaf(p, f, 1.0f);
    return __int_as_float(__float_as_int(p) + (i << 23));
}

// ---------------- K1: fused QKV projection ----------------
// Y[32768,192] = X[32768,1024] @ [Wq|Wk|Wv] + bias.  BM=128, BN=192(all), BK=32.
// q,k written transposed [b][d][t]; v written [b][t][d].
__global__ __launch_bounds__(256) void qkv_kernel(
    const float* __restrict__ x,
    const float* __restrict__ Wq, const float* __restrict__ bq,
    const float* __restrict__ Wk, const float* __restrict__ bk,
    const float* __restrict__ Wv, const float* __restrict__ bv)
{
    __shared__ float Xs[32][132];   // [k][m], padded
    __shared__ float Ws[32][192];   // [k][n]
    const int tid = threadIdx.x;
    const int ty = tid & 15;        // m-chunk (8 rows)
    const int tx = tid >> 4;        // n-chunk (12 cols)
    const int m0 = ty * 8, n0 = tx * 12;
    const int mblk = blockIdx.x * 128;

    float acc[8][12];
    #pragma unroll
    for (int i = 0; i < 8; i++)
        #pragma unroll
        for (int j = 0; j < 12; j++) acc[i][j] = 0.0f;

    for (int k0 = 0; k0 < Cn; k0 += 32) {
        // Xs: 128 x 32 floats, transposed store
        #pragma unroll
        for (int i = 0; i < 4; i++) {
            int idx = tid + i * 256;       // float4 index
            int mm  = idx >> 3;            // 8 f4 per row
            int kk  = (idx & 7) * 4;
            float4 vx = *(const float4*)(x + (size_t)(mblk + mm) * Cn + k0 + kk);
            Xs[kk    ][mm] = vx.x;
            Xs[kk + 1][mm] = vx.y;
            Xs[kk + 2][mm] = vx.z;
            Xs[kk + 3][mm] = vx.w;
        }
        // Ws: 32 x 192 floats
        #pragma unroll
        for (int i = 0; i < 6; i++) {
            int idx = tid + i * 256;
            int kk  = idx / 48;
            int nf  = (idx % 48) * 4;
            const float* wsrc = (nf < 64) ? Wq : (nf < 128) ? Wk : Wv;
            int col = nf & 63;
            *(float4*)&Ws[kk][nf] = *(const float4*)(wsrc + (size_t)(k0 + kk) * Hn + col);
        }
        __syncthreads();
        #pragma unroll 8
        for (int kk = 0; kk < 32; kk++) {
            float a[8], bb[12];
            *(float4*)&a[0] = *(float4*)&Xs[kk][m0];
            *(float4*)&a[4] = *(float4*)&Xs[kk][m0 + 4];
            *(float4*)&bb[0] = *(float4*)&Ws[kk][n0];
            *(float4*)&bb[4] = *(float4*)&Ws[kk][n0 + 4];
            *(float4*)&bb[8] = *(float4*)&Ws[kk][n0 + 8];
            #pragma unroll
            for (int i = 0; i < 8; i++)
                #pragma unroll
                for (int j = 0; j < 12; j++)
                    acc[i][j] = fmaf(a[i], bb[j], acc[i][j]);
        }
        __syncthreads();
    }

    const int b = mblk >> 11;
    const int tbase = (mblk & 2047) + m0;
    #pragma unroll
    for (int j = 0; j < 12; j++) {
        int n = n0 + j;
        int mat = n >> 6, col = n & 63;
        float bias = (mat == 0) ? bq[col] : (mat == 1) ? bk[col] : bv[col];
        if (mat < 2) {
            float* dst = ((mat == 0) ? g_qT : g_kT) + ((size_t)b * Hn + col) * Tn + tbase;
            float4 v0 = make_float4(acc[0][j] + bias, acc[1][j] + bias,
                                    acc[2][j] + bias, acc[3][j] + bias);
            float4 v1 = make_float4(acc[4][j] + bias, acc[5][j] + bias,
                                    acc[6][j] + bias, acc[7][j] + bias);
            *(float4*)(dst)     = v0;
            *(float4*)(dst + 4) = v1;
        } else {
            float* dst = g_v + ((size_t)b * Tn + tbase) * Hn + col;
            #pragma unroll
            for (int i = 0; i < 8; i++) dst[(size_t)i * Hn] = acc[i][j] + bias;
        }
    }
}

// ---------------- K2: S = Q K^T (triangular tiles), write S^T + column stats ----------------
// Tile 128(t) x 128(s), K=64 in two halves of 32. Writes S^T[b][s][t].
__global__ __launch_bounds__(256) void scores_kernel()
{
    const int bt = blockIdx.x, bs = blockIdx.y, b = blockIdx.z;
    if (bt < bs) return;
    __shared__ float Qs[32][132];   // [d][t]
    __shared__ float Ks[32][132];   // [d][s]
    const int tid = threadIdx.x;
    const int ty = tid & 15;        // t-chunk
    const int tx = tid >> 4;        // s-chunk
    const int t0 = ty * 8, s0 = tx * 8;

    float acc[8][8];
    #pragma unroll
    for (int i = 0; i < 8; i++)
        #pragma unroll
        for (int j = 0; j < 8; j++) acc[i][j] = 0.0f;

    const float* qb = g_qT + (size_t)b * Hn * Tn;
    const float* kb = g_kT + (size_t)b * Hn * Tn;

    for (int kh = 0; kh < Hn; kh += 32) {
        #pragma unroll
        for (int i = 0; i < 4; i++) {
            int idx = tid + i * 256;    // f4 index, 32 f4 per row
            int d   = idx >> 5;
            int c4  = (idx & 31) * 4;
            *(float4*)&Qs[d][c4] = *(const float4*)(qb + (size_t)(kh + d) * Tn + bt * 128 + c4);
            *(float4*)&Ks[d][c4] = *(const float4*)(kb + (size_t)(kh + d) * Tn + bs * 128 + c4);
        }
        __syncthreads();
        #pragma unroll 8
        for (int kk = 0; kk < 32; kk++) {
            float a[8], bb[8];
            *(float4*)&a[0]  = *(float4*)&Qs[kk][t0];
            *(float4*)&a[4]  = *(float4*)&Qs[kk][t0 + 4];
            *(float4*)&bb[0] = *(float4*)&Ks[kk][s0];
            *(float4*)&bb[4] = *(float4*)&Ks[kk][s0 + 4];
            #pragma unroll
            for (int i = 0; i < 8; i++)
                #pragma unroll
                for (int j = 0; j < 8; j++)
                    acc[i][j] = fmaf(a[i], bb[j], acc[i][j]);
        }
        __syncthreads();
    }

    const int gt0 = bt * 128 + t0;
    const int gs0 = bs * 128 + s0;
    // causal mask: keep t >= s
    #pragma unroll
    for (int i = 0; i < 8; i++)
        #pragma unroll
        for (int j = 0; j < 8; j++)
            if (gs0 + j > gt0 + i) acc[i][j] = -1e30f;

    float* STb = g_ST + (size_t)b * Tn * Tn;
    #pragma unroll
    for (int j = 0; j < 8; j++) {
        float4 v0 = make_float4(acc[0][j], acc[1][j], acc[2][j], acc[3][j]);
        float4 v1 = make_float4(acc[4][j], acc[5][j], acc[6][j], acc[7][j]);
        float* dst = STb + (size_t)(gs0 + j) * Tn + gt0;
        *(float4*)(dst)     = v0;
        *(float4*)(dst + 4) = v1;
    }

    // per-column (s) stats over this tile's 128 t values
    #pragma unroll
    for (int j = 0; j < 8; j++) {
        float m = acc[0][j];
        #pragma unroll
        for (int i = 1; i < 8; i++) m = fmaxf(m, acc[i][j]);
        #pragma unroll
        for (int off = 1; off < 16; off <<= 1)
            m = fmaxf(m, __shfl_xor_sync(0xffffffffu, m, off));
        float zv = 0.0f;
        #pragma unroll
        for (int i = 0; i < 8; i++) zv += fast_exp(acc[i][j] - m);
        #pragma unroll
        for (int off = 1; off < 16; off <<= 1)
            zv += __shfl_xor_sync(0xffffffffu, zv, off);
        if (ty == 0) {
            g_mpart[((size_t)b * 16 + bt) * Tn + gs0 + j] = m;
            g_zpart[((size_t)b * 16 + bt) * Tn + gs0 + j] = zv;
        }
    }
}

// ---------------- K2b: merge (m,z) partials -> c[b][s] = m + log Z ----------------
__global__ __launch_bounds__(256) void stats_kernel()
{
    int idx = blockIdx.x * 256 + threadIdx.x;   // b*2048 + s
    int b = idx >> 11, s = idx & 2047;
    int bt0 = s >> 7;
    float m = -1e30f;
    for (int bt = bt0; bt < 16; bt++)
        m = fmaxf(m, g_mpart[((size_t)b * 16 + bt) * Tn + s]);
    float zv = 0.0f;
    for (int bt = bt0; bt < 16; bt++)
        zv += g_zpart[((size_t)b * 16 + bt) * Tn + s] *
              expf(g_mpart[((size_t)b * 16 + bt) * Tn + s] - m);
    g_c[idx] = m + logf(zv);
}

// ---------------- K4: out[t,d] = sum_s exp(S^T[s][t] - c[s]) * v[s,d] ----------------
// Block = 128 t rows x 64 d cols; loops s in chunks of 32.
__global__ __launch_bounds__(256) void out_kernel(float* __restrict__ out)
{
    const int bt = 15 - blockIdx.x;   // longest blocks scheduled first
    const int b  = blockIdx.y;
    __shared__ float Ps[32][132];     // [s][t] = exp(S^T - c)
    __shared__ float Vs[32][64];      // [s][d]
    const int tid = threadIdx.x;
    const int ty = tid & 15;          // t-chunk (8)
    const int tx = tid >> 4;          // d-chunk (4)
    const int t0 = ty * 8, d0 = tx * 4;

    float acc[8][4];
    #pragma unroll
    for (int i = 0; i < 8; i++)
        #pragma unroll
        for (int j = 0; j < 4; j++) acc[i][j] = 0.0f;

    const float* STb = g_ST + (size_t)b * Tn * Tn + bt * 128;
    const float* vb  = g_v  + (size_t)b * Tn * Hn;
    const float* cb  = g_c  + b * Tn;
    const int smax = bt * 128 + 128;

    for (int sg = 0; sg < smax; sg += 32) {
        #pragma unroll
        for (int i = 0; i < 4; i++) {
            int idx = tid + i * 256;       // f4 index
            int r   = idx >> 5;            // 32 f4 per row of 128
            int c4  = (idx & 31) * 4;
            float cc = cb[sg + r];
            float4 sv = *(const float4*)(STb + (size_t)(sg + r) * Tn + c4);
            float4 pv = make_float4(fast_exp(sv.x - cc), fast_exp(sv.y - cc),
                                    fast_exp(sv.z - cc), fast_exp(sv.w - cc));
            *(float4*)&Ps[r][c4] = pv;
        }
        #pragma unroll
        for (int i = 0; i < 2; i++) {
            int idx = tid + i * 256;
            int r   = idx >> 4;            // 16 f4 per row of 64
            int c4  = (idx & 15) * 4;
            *(float4*)&Vs[r][c4] = *(const float4*)(vb + (size_t)(sg + r) * Hn + c4);
        }
        __syncthreads();
        #pragma unroll 8
        for (int ss = 0; ss < 32; ss++) {
            float a[8], bb[4];
            *(float4*)&a[0]  = *(float4*)&Ps[ss][t0];
            *(float4*)&a[4]  = *(float4*)&Ps[ss][t0 + 4];
            *(float4*)&bb[0] = *(float4*)&Vs[ss][d0];
            #pragma unroll
            for (int i = 0; i < 8; i++)
                #pragma unroll
                for (int j = 0; j < 4; j++)
                    acc[i][j] = fmaf(a[i], bb[j], acc[i][j]);
        }
        __syncthreads();
    }

    const int gt0 = bt * 128 + t0;
    #pragma unroll
    for (int i = 0; i < 8; i++) {
        float4 v = make_float4(acc[i][0], acc[i][1], acc[i][2], acc[i][3]);
        *(float4*)(out + ((size_t)b * Tn + gt0 + i) * Hn + d0) = v;
    }
}

extern "C" void kernel_launch(void* const* d_in, const int* in_sizes, int n_in,
                              void* d_out, int out_size)
{
    const float* x  = (const float*)d_in[0];
    const float* Wq = (const float*)d_in[1];
    const float* bq = (const float*)d_in[2];
    const float* Wk = (const float*)d_in[3];
    const float* bk = (const float*)d_in[4];
    const float* Wv = (const float*)d_in[5];
    const float* bv = (const float*)d_in[6];
    float* out = (float*)d_out;

    qkv_kernel<<<256, 256>>>(x, Wq, bq, Wk, bk, Wv, bv);
    scores_kernel<<<dim3(16, 16, 16), 256>>>();
    stats_kernel<<<128, 256>>>();
    out_kernel<<<dim3(16, 16), 256>>>(out);
}